// round 9
// baseline (speedup 1.0000x reference)
#include <cuda_runtime.h>
#include <math.h>
#include <stdint.h>

// Problem constants
#define BB 32
#define TT 64
#define EE 512
#define HH 512
#define VV 32000
#define NSTEP 63              // T-1 timesteps
#define MM (NSTEP * BB)       // 2016 rows
#define G4 (4 * HH)           // 2048 gate columns
#define KK 512

// -------------------- device scratch (no allocs allowed) --------------------
__device__ float g_xseq[MM * EE];          // [63*32][512]  LSTM inputs
__device__ float g_pre[(size_t)MM * G4];   // [2016][2048]  pre-gates (x@W_ih^T + biases)
__device__ float g_hs[MM * HH];            // [2016][512]   hidden states per step
__device__ float g_h[2][BB * HH];          // double-buffered h (cross-CTA race safety)
__device__ float g_c[BB * HH];             // cell state (CTA-private columns)
__device__ int   g_cap64;                  // 1 if captions buffer is int64

// -------------------- dtype detect for captions --------------------
__global__ void detect_cap64(const int* cap) {
    if (threadIdx.x == 0) {
        int f = 1;
        for (int i = 0; i < 32; i++)
            if (cap[2 * i + 1] != 0) { f = 0; break; }
        g_cap64 = f;
    }
}

// -------------------- init h/c to zero (every launch: graph-replay determinism) ----
__global__ void init_state() {
    int i = blockIdx.x * blockDim.x + threadIdx.x;
    if (i < BB * HH) { g_h[0][i] = 0.f; g_c[i] = 0.f; }
}

// -------------------- zero out[:, 0, :] --------------------
__global__ void zero_out0(float* out) {
    int b  = blockIdx.y;
    int vv = blockIdx.x * 256 + threadIdx.x;
    if (vv < VV) out[(size_t)b * TT * VV + vv] = 0.f;
}

// -------------------- build x_seq: [t=0]=features, [t>=1]=embed(captions[:,t+1]) ----
__global__ void build_xseq(const float* __restrict__ features,
                           const void*  __restrict__ cap,
                           const float* __restrict__ embed) {
    int i = blockIdx.x;   // 0..62
    int b = blockIdx.y;   // 0..31
    int col = threadIdx.x * 4;
    const float* src;
    if (i == 0) {
        src = features + (size_t)b * EE;
    } else {
        long long idx;
        if (g_cap64) idx = ((const long long*)cap)[b * TT + i + 1];
        else         idx = ((const int*)cap)[b * TT + i + 1];
        src = embed + (size_t)idx * EE;
    }
    *(float4*)&g_xseq[((size_t)i * BB + b) * EE + col] = *(const float4*)&src[col];
}

// -------------------- tf32 helpers --------------------
__device__ __forceinline__ uint32_t f2tf32(float x) {
    uint32_t u;
    asm("cvt.rna.tf32.f32 %0, %1;" : "=r"(u) : "f"(x));
    return u;
}

// -------------------- tf32 GEMM: out = A @ B^T + bias (ROUND-1 PROVEN MATH) -------
// Identical indexing/fragments/FP-order to the round-1 passing kernel; the ONLY
// change is scheduling: tile kt+1's global loads are issued into registers
// BEFORE tile kt's compute, hiding LDG latency under the MMA stream.
// A row-major [M, 512] (device global picked by MODE), B row-major [N, 512].
// MODE 0: A=g_xseq, out=g_pre[m][n],              bias = bias1[n]+bias2[n]
// MODE 1: A=g_hs,   out=d_out[(b*64 + t+1)][n],   bias = bias1[n]   (m = t*32+b)
template <int MODE, int N>
__global__ void __launch_bounds__(256)
gemm_tf32(const float* __restrict__ Bmat,
          const float* __restrict__ bias1,
          const float* __restrict__ bias2,
          float* __restrict__ outc) {
    constexpr int BM = 128, BN = 64, BK = 16;
    __shared__ uint32_t sA[BM][BK + 4];
    __shared__ uint32_t sB[BN][BK + 4];

    const float* Amat = (MODE == 0) ? g_xseq : g_hs;
    float*       Out  = (MODE == 0) ? g_pre  : outc;

    int tid  = threadIdx.x;
    int wid  = tid >> 5, lane = tid & 31;
    int wm   = wid & 3,  wn   = wid >> 2;      // 4x2 warp grid, warp tile 32x32
    int grp  = lane >> 2, tig = lane & 3;
    int m0   = blockIdx.y * BM, n0 = blockIdx.x * BN;

    // fixed per-thread load coordinates (same as round 1)
    int arow[2], acol[2];
#pragma unroll
    for (int l = 0; l < 2; l++) {
        int s = tid + l * 256;            // 0..511 float4 slots (128 rows x 4)
        arow[l] = s >> 2; acol[l] = (s & 3) * 4;
    }
    int br = tid >> 2, bc = (tid & 3) * 4;   // 64 rows x 4 float4

    float c[2][4][4];
#pragma unroll
    for (int mi = 0; mi < 2; mi++)
#pragma unroll
        for (int ni = 0; ni < 4; ni++)
#pragma unroll
            for (int r = 0; r < 4; r++) c[mi][ni][r] = 0.f;

    // prologue: load tile 0 into registers
    float4 av[2], bv;
#pragma unroll
    for (int l = 0; l < 2; l++) {
        int gm = m0 + arow[l];
        if (gm < MM) av[l] = *(const float4*)&Amat[(size_t)gm * KK + acol[l]];
        else         av[l] = make_float4(0.f, 0.f, 0.f, 0.f);
    }
    bv = *(const float4*)&Bmat[(size_t)(n0 + br) * KK + bc];

    for (int kt = 0; kt < KK / BK; kt++) {
        __syncthreads();   // previous iter's compute done before overwrite
#pragma unroll
        for (int l = 0; l < 2; l++) {
            uint32_t* p = &sA[arow[l]][acol[l]];
            p[0] = f2tf32(av[l].x); p[1] = f2tf32(av[l].y);
            p[2] = f2tf32(av[l].z); p[3] = f2tf32(av[l].w);
        }
        {
            uint32_t* p = &sB[br][bc];
            p[0] = f2tf32(bv.x); p[1] = f2tf32(bv.y);
            p[2] = f2tf32(bv.z); p[3] = f2tf32(bv.w);
        }
        __syncthreads();

        // prefetch tile kt+1 into registers (overlaps with compute below)
        if (kt + 1 < KK / BK) {
            int k0 = (kt + 1) * BK;
#pragma unroll
            for (int l = 0; l < 2; l++) {
                int gm = m0 + arow[l];
                if (gm < MM) av[l] = *(const float4*)&Amat[(size_t)gm * KK + k0 + acol[l]];
                else         av[l] = make_float4(0.f, 0.f, 0.f, 0.f);
            }
            bv = *(const float4*)&Bmat[(size_t)(n0 + br) * KK + k0 + bc];
        }

#pragma unroll
        for (int ks = 0; ks < 2; ks++) {
            int kk = ks * 8;
            uint32_t a[2][4], bf[4][2];
#pragma unroll
            for (int mi = 0; mi < 2; mi++) {
                int mr = wm * 32 + mi * 16;
                a[mi][0] = sA[mr + grp][kk + tig];
                a[mi][1] = sA[mr + grp + 8][kk + tig];
                a[mi][2] = sA[mr + grp][kk + tig + 4];
                a[mi][3] = sA[mr + grp + 8][kk + tig + 4];
            }
#pragma unroll
            for (int ni = 0; ni < 4; ni++) {
                int nr = wn * 32 + ni * 8;
                bf[ni][0] = sB[nr + grp][kk + tig];
                bf[ni][1] = sB[nr + grp][kk + tig + 4];
            }
#pragma unroll
            for (int mi = 0; mi < 2; mi++)
#pragma unroll
                for (int ni = 0; ni < 4; ni++) {
                    asm volatile(
                        "mma.sync.aligned.m16n8k8.row.col.f32.tf32.tf32.f32 "
                        "{%0,%1,%2,%3}, {%4,%5,%6,%7}, {%8,%9}, {%0,%1,%2,%3};"
                        : "+f"(c[mi][ni][0]), "+f"(c[mi][ni][1]),
                          "+f"(c[mi][ni][2]), "+f"(c[mi][ni][3])
                        : "r"(a[mi][0]), "r"(a[mi][1]), "r"(a[mi][2]), "r"(a[mi][3]),
                          "r"(bf[ni][0]), "r"(bf[ni][1]));
                }
        }
    }

    // epilogue (round-1 proven)
#pragma unroll
    for (int mi = 0; mi < 2; mi++) {
#pragma unroll
        for (int ni = 0; ni < 4; ni++) {
            int col = n0 + wn * 32 + ni * 8 + tig * 2;
            float bs0 = bias1[col]     + (MODE == 0 ? bias2[col]     : 0.f);
            float bs1 = bias1[col + 1] + (MODE == 0 ? bias2[col + 1] : 0.f);
#pragma unroll
            for (int half = 0; half < 2; half++) {
                int mrow = m0 + wm * 32 + mi * 16 + grp + half * 8;
                if (mrow < MM) {
                    size_t off;
                    if (MODE == 0) {
                        off = (size_t)mrow * N;
                    } else {
                        int t = mrow >> 5, b = mrow & 31;
                        off = ((size_t)(b * TT + t + 1)) * N;
                    }
                    Out[off + col]     = c[mi][ni][half * 2 + 0] + bs0;
                    Out[off + col + 1] = c[mi][ni][half * 2 + 1] + bs1;
                }
            }
        }
    }
}

// -------------------- LSTM step (ROUND-1 PROVEN, fp32) --------------------
// grid 128 CTAs (4 hidden units each), 256 threads (8 warps).
// Warp w computes gate rows r = 2w, 2w+1 of this CTA's 16 gate rows,
// for all 32 batches (lane = batch). r = g*4 + du, j = g*512 + (cta*4+du).
#define LSTM_SMEM ((32 * 516 + 16 * 32) * 4)

__global__ void lstm_step(const float* __restrict__ Whh, int t) {
    extern __shared__ float sm[];
    float* shh = sm;             // [32][516] padded h (prev step)
    float* sg  = sm + 32 * 516;  // [16][32] gate values

    int tid = threadIdx.x;
    const float* hin = g_h[t & 1];
#pragma unroll
    for (int i = 0; i < 16; i++) {
        int s = tid + i * 256;           // 4096 float4 slots
        int row = s >> 7, c4 = s & 127;
        float4 v = *(const float4*)&hin[row * 512 + c4 * 4];
        *(float4*)&shh[row * 516 + c4 * 4] = v;
    }
    __syncthreads();

    int wid = tid >> 5, lane = tid & 31;
#pragma unroll
    for (int rr = 0; rr < 2; rr++) {
        int r = wid * 2 + rr;
        int gidx = r >> 2, du = r & 3;
        int u = blockIdx.x * 4 + du;
        int j = gidx * 512 + u;
        const float4* wp = (const float4*)(Whh + (size_t)j * 512);
        const float4* hp = (const float4*)&shh[lane * 516];
        float acc = 0.f;
#pragma unroll 4
        for (int kkk = 0; kkk < 128; kkk++) {
            float4 w4 = __ldg(&wp[kkk]);    // uniform across warp (broadcast)
            float4 h4 = hp[kkk];
            acc += w4.x * h4.x + w4.y * h4.y + w4.z * h4.z + w4.w * h4.w;
        }
        acc += g_pre[((size_t)t * 32 + lane) * (size_t)G4 + j];
        sg[r * 32 + lane] = acc;
    }
    __syncthreads();

    if (tid < 128) {
        int du = tid >> 5, b = tid & 31;
        int u  = blockIdx.x * 4 + du;
        float gi = sg[(0 + du) * 32 + b];
        float gf = sg[(4 + du) * 32 + b];
        float gg = sg[(8 + du) * 32 + b];
        float go = sg[(12 + du) * 32 + b];
        float si = 1.f / (1.f + __expf(-gi));
        float sf = 1.f / (1.f + __expf(-gf));
        float so = 1.f / (1.f + __expf(-go));
        float tg = tanhf(gg);
        float cn = sf * g_c[b * 512 + u] + si * tg;
        float hn = so * tanhf(cn);
        g_c[b * 512 + u] = cn;
        g_h[(t + 1) & 1][b * 512 + u] = hn;
        g_hs[((size_t)t * 32 + b) * 512 + u] = hn;
    }
}

// -------------------- launch --------------------
extern "C" void kernel_launch(void* const* d_in, const int* in_sizes, int n_in,
                              void* d_out, int out_size) {
    const float* features = (const float*)d_in[0];
    const void*  captions = d_in[1];
    const float* embed    = (const float*)d_in[2];
    const float* W_ih     = (const float*)d_in[3];
    const float* W_hh     = (const float*)d_in[4];
    const float* b_ih     = (const float*)d_in[5];
    const float* b_hh     = (const float*)d_in[6];
    const float* fc_w     = (const float*)d_in[7];
    const float* fc_b     = (const float*)d_in[8];
    float* out = (float*)d_out;

    cudaFuncSetAttribute(lstm_step, cudaFuncAttributeMaxDynamicSharedMemorySize,
                         LSTM_SMEM);

    detect_cap64<<<1, 32>>>((const int*)captions);
    init_state<<<64, 256>>>();
    zero_out0<<<dim3(125, 32), 256>>>(out);
    build_xseq<<<dim3(63, 32), 128>>>(features, captions, embed);

    // pre-gates for all timesteps: [2016,512] @ [512,2048]
    gemm_tf32<0, G4><<<dim3(G4 / 64, 16), 256>>>(W_ih, b_ih, b_hh, nullptr);

    // sequential recurrence
    for (int t = 0; t < NSTEP; t++)
        lstm_step<<<128, 256, LSTM_SMEM>>>(W_hh, t);

    // output projection: [2016,512] @ [512,32000], scattered to out[b][t+1][:]
    gemm_tf32<1, VV><<<dim3(VV / 64, 16), 256>>>(fc_w, fc_b, nullptr, out);
}

// round 11
// speedup vs baseline: 1.0525x; 1.0525x over previous
#include <cuda_runtime.h>
#include <math.h>
#include <stdint.h>

// Problem constants
#define BB 32
#define TT 64
#define EE 512
#define HH 512
#define VV 32000
#define NSTEP 63              // T-1 timesteps
#define MM (NSTEP * BB)       // 2016 rows
#define G4 (4 * HH)           // 2048 gate columns
#define KK 512

// -------------------- device scratch (no allocs allowed) --------------------
__device__ float g_xseq[MM * EE];          // [63*32][512]  LSTM inputs
__device__ float g_pre[(size_t)MM * G4];   // [2016][2048]  pre-gates (x@W_ih^T + biases)
__device__ float g_hs[MM * HH];            // [2016][512]   hidden states per step
__device__ float g_h[2][BB * HH];          // double-buffered h (cross-CTA race safety)
__device__ float g_c[BB * HH];             // cell state (CTA-private columns)
__device__ int   g_cap64;                  // 1 if captions buffer is int64

// -------------------- dtype detect for captions --------------------
__global__ void detect_cap64(const int* cap) {
    if (threadIdx.x == 0) {
        int f = 1;
        for (int i = 0; i < 32; i++)
            if (cap[2 * i + 1] != 0) { f = 0; break; }
        g_cap64 = f;
    }
}

// -------------------- init h/c to zero (every launch: graph-replay determinism) ----
__global__ void init_state() {
    int i = blockIdx.x * blockDim.x + threadIdx.x;
    if (i < BB * HH) { g_h[0][i] = 0.f; g_c[i] = 0.f; }
}

// -------------------- zero out[:, 0, :] --------------------
__global__ void zero_out0(float* out) {
    int b  = blockIdx.y;
    int vv = blockIdx.x * 256 + threadIdx.x;
    if (vv < VV) out[(size_t)b * TT * VV + vv] = 0.f;
}

// -------------------- build x_seq: [t=0]=features, [t>=1]=embed(captions[:,t+1]) ----
__global__ void build_xseq(const float* __restrict__ features,
                           const void*  __restrict__ cap,
                           const float* __restrict__ embed) {
    int i = blockIdx.x;   // 0..62
    int b = blockIdx.y;   // 0..31
    int col = threadIdx.x * 4;
    const float* src;
    if (i == 0) {
        src = features + (size_t)b * EE;
    } else {
        long long idx;
        if (g_cap64) idx = ((const long long*)cap)[b * TT + i + 1];
        else         idx = ((const int*)cap)[b * TT + i + 1];
        src = embed + (size_t)idx * EE;
    }
    *(float4*)&g_xseq[((size_t)i * BB + b) * EE + col] = *(const float4*)&src[col];
}

// -------------------- tf32 helpers --------------------
__device__ __forceinline__ uint32_t f2tf32(float x) {
    uint32_t u;
    asm("cvt.rna.tf32.f32 %0, %1;" : "=r"(u) : "f"(x));
    return u;
}

// -------------------- tf32 GEMM: out = A @ B^T + bias --------------------
// ROUND-1 PROVEN structure, widened BN 64 -> 128 (only the N-extent scales:
// B load map now mirrors A's proven map; per-element K order is unchanged,
// so output is bitwise identical to round 1).
// A row-major [M, 512] (device global picked by MODE), B row-major [N, 512].
// MODE 0: A=g_xseq, out=g_pre[m][n],              bias = bias1[n]+bias2[n]
// MODE 1: A=g_hs,   out=d_out[(b*64 + t+1)][n],   bias = bias1[n]   (m = t*32+b)
template <int MODE, int N>
__global__ void __launch_bounds__(256)
gemm_tf32(const float* __restrict__ Bmat,
          const float* __restrict__ bias1,
          const float* __restrict__ bias2,
          float* __restrict__ outc) {
    constexpr int BM = 128, BN = 128, BK = 16;
    __shared__ uint32_t sA[BM][BK + 4];
    __shared__ uint32_t sB[BN][BK + 4];

    const float* Amat = (MODE == 0) ? g_xseq : g_hs;
    float*       Out  = (MODE == 0) ? g_pre  : outc;

    int tid  = threadIdx.x;
    int wid  = tid >> 5, lane = tid & 31;
    int wm   = wid & 3,  wn   = wid >> 2;      // 4x2 warp grid, warp tile 32x64
    int grp  = lane >> 2, tig = lane & 3;
    int m0   = blockIdx.y * BM, n0 = blockIdx.x * BN;

    float c[2][8][4];
#pragma unroll
    for (int mi = 0; mi < 2; mi++)
#pragma unroll
        for (int ni = 0; ni < 8; ni++)
#pragma unroll
            for (int r = 0; r < 4; r++) c[mi][ni][r] = 0.f;

    for (int kt = 0; kt < KK / BK; kt++) {
        int k0 = kt * BK;
        // global -> regs (A: 128 rows x 16 cols; B: 128 rows x 16 cols, same map)
        float4 av[2], bv[2]; int arow[2], acol[2];
#pragma unroll
        for (int l = 0; l < 2; l++) {
            int s = tid + l * 256;            // 0..511 float4 slots (128 rows x 4)
            int r = s >> 2, cq = s & 3;
            arow[l] = r; acol[l] = cq * 4;
            int gm = m0 + r;
            if (gm < MM) av[l] = *(const float4*)&Amat[(size_t)gm * KK + k0 + cq * 4];
            else         av[l] = make_float4(0.f, 0.f, 0.f, 0.f);
            bv[l] = *(const float4*)&Bmat[(size_t)(n0 + r) * KK + k0 + cq * 4];
        }

        __syncthreads();   // previous iter's compute done before overwrite
#pragma unroll
        for (int l = 0; l < 2; l++) {
            uint32_t* p = &sA[arow[l]][acol[l]];
            p[0] = f2tf32(av[l].x); p[1] = f2tf32(av[l].y);
            p[2] = f2tf32(av[l].z); p[3] = f2tf32(av[l].w);
            uint32_t* q = &sB[arow[l]][acol[l]];
            q[0] = f2tf32(bv[l].x); q[1] = f2tf32(bv[l].y);
            q[2] = f2tf32(bv[l].z); q[3] = f2tf32(bv[l].w);
        }
        __syncthreads();

#pragma unroll
        for (int ks = 0; ks < 2; ks++) {
            int kk = ks * 8;
            uint32_t a[2][4], bf[8][2];
#pragma unroll
            for (int mi = 0; mi < 2; mi++) {
                int mr = wm * 32 + mi * 16;
                a[mi][0] = sA[mr + grp][kk + tig];
                a[mi][1] = sA[mr + grp + 8][kk + tig];
                a[mi][2] = sA[mr + grp][kk + tig + 4];
                a[mi][3] = sA[mr + grp + 8][kk + tig + 4];
            }
#pragma unroll
            for (int ni = 0; ni < 8; ni++) {
                int nr = wn * 64 + ni * 8;
                bf[ni][0] = sB[nr + grp][kk + tig];
                bf[ni][1] = sB[nr + grp][kk + tig + 4];
            }
#pragma unroll
            for (int mi = 0; mi < 2; mi++)
#pragma unroll
                for (int ni = 0; ni < 8; ni++) {
                    asm volatile(
                        "mma.sync.aligned.m16n8k8.row.col.f32.tf32.tf32.f32 "
                        "{%0,%1,%2,%3}, {%4,%5,%6,%7}, {%8,%9}, {%0,%1,%2,%3};"
                        : "+f"(c[mi][ni][0]), "+f"(c[mi][ni][1]),
                          "+f"(c[mi][ni][2]), "+f"(c[mi][ni][3])
                        : "r"(a[mi][0]), "r"(a[mi][1]), "r"(a[mi][2]), "r"(a[mi][3]),
                          "r"(bf[ni][0]), "r"(bf[ni][1]));
                }
        }
    }

    // epilogue
#pragma unroll
    for (int mi = 0; mi < 2; mi++) {
#pragma unroll
        for (int ni = 0; ni < 8; ni++) {
            int col = n0 + wn * 64 + ni * 8 + tig * 2;
            float bs0 = bias1[col]     + (MODE == 0 ? bias2[col]     : 0.f);
            float bs1 = bias1[col + 1] + (MODE == 0 ? bias2[col + 1] : 0.f);
#pragma unroll
            for (int half = 0; half < 2; half++) {
                int mrow = m0 + wm * 32 + mi * 16 + grp + half * 8;
                if (mrow < MM) {
                    size_t off;
                    if (MODE == 0) {
                        off = (size_t)mrow * N;
                    } else {
                        int t = mrow >> 5, b = mrow & 31;
                        off = ((size_t)(b * TT + t + 1)) * N;
                    }
                    Out[off + col]     = c[mi][ni][half * 2 + 0] + bs0;
                    Out[off + col + 1] = c[mi][ni][half * 2 + 1] + bs1;
                }
            }
        }
    }
}

// -------------------- LSTM step (ROUND-1 PROVEN, fp32, per-step launch) ----------
// grid 128 CTAs (4 hidden units each), 256 threads (8 warps).
// Warp w computes gate rows r = 2w, 2w+1 of this CTA's 16 gate rows,
// for all 32 batches (lane = batch). r = g*4 + du, j = g*512 + (cta*4+du).
#define LSTM_SMEM ((32 * 516 + 16 * 32) * 4)

__global__ void lstm_step(const float* __restrict__ Whh, int t) {
    extern __shared__ float sm[];
    float* shh = sm;             // [32][516] padded h (prev step)
    float* sg  = sm + 32 * 516;  // [16][32] gate values

    int tid = threadIdx.x;
    const float* hin = g_h[t & 1];
#pragma unroll
    for (int i = 0; i < 16; i++) {
        int s = tid + i * 256;           // 4096 float4 slots
        int row = s >> 7, c4 = s & 127;
        float4 v = *(const float4*)&hin[row * 512 + c4 * 4];
        *(float4*)&shh[row * 516 + c4 * 4] = v;
    }
    __syncthreads();

    int wid = tid >> 5, lane = tid & 31;
#pragma unroll
    for (int rr = 0; rr < 2; rr++) {
        int r = wid * 2 + rr;
        int gidx = r >> 2, du = r & 3;
        int u = blockIdx.x * 4 + du;
        int j = gidx * 512 + u;
        const float4* wp = (const float4*)(Whh + (size_t)j * 512);
        const float4* hp = (const float4*)&shh[lane * 516];
        float acc = 0.f;
#pragma unroll 4
        for (int kkk = 0; kkk < 128; kkk++) {
            float4 w4 = __ldg(&wp[kkk]);    // uniform across warp (broadcast)
            float4 h4 = hp[kkk];
            acc += w4.x * h4.x + w4.y * h4.y + w4.z * h4.z + w4.w * h4.w;
        }
        acc += g_pre[((size_t)t * 32 + lane) * (size_t)G4 + j];
        sg[r * 32 + lane] = acc;
    }
    __syncthreads();

    if (tid < 128) {
        int du = tid >> 5, b = tid & 31;
        int u  = blockIdx.x * 4 + du;
        float gi = sg[(0 + du) * 32 + b];
        float gf = sg[(4 + du) * 32 + b];
        float gg = sg[(8 + du) * 32 + b];
        float go = sg[(12 + du) * 32 + b];
        float si = 1.f / (1.f + __expf(-gi));
        float sf = 1.f / (1.f + __expf(-gf));
        float so = 1.f / (1.f + __expf(-go));
        float tg = tanhf(gg);
        float cn = sf * g_c[b * 512 + u] + si * tg;
        float hn = so * tanhf(cn);
        g_c[b * 512 + u] = cn;
        g_h[(t + 1) & 1][b * 512 + u] = hn;
        g_hs[((size_t)t * 32 + b) * 512 + u] = hn;
    }
}

// -------------------- launch --------------------
extern "C" void kernel_launch(void* const* d_in, const int* in_sizes, int n_in,
                              void* d_out, int out_size) {
    const float* features = (const float*)d_in[0];
    const void*  captions = d_in[1];
    const float* embed    = (const float*)d_in[2];
    const float* W_ih     = (const float*)d_in[3];
    const float* W_hh     = (const float*)d_in[4];
    const float* b_ih     = (const float*)d_in[5];
    const float* b_hh     = (const float*)d_in[6];
    const float* fc_w     = (const float*)d_in[7];
    const float* fc_b     = (const float*)d_in[8];
    float* out = (float*)d_out;

    cudaFuncSetAttribute(lstm_step, cudaFuncAttributeMaxDynamicSharedMemorySize,
                         LSTM_SMEM);

    detect_cap64<<<1, 32>>>((const int*)captions);
    init_state<<<64, 256>>>();
    zero_out0<<<dim3(125, 32), 256>>>(out);
    build_xseq<<<dim3(63, 32), 128>>>(features, captions, embed);

    // pre-gates for all timesteps: [2016,512] @ [512,2048]
    gemm_tf32<0, G4><<<dim3(G4 / 128, 16), 256>>>(W_ih, b_ih, b_hh, nullptr);

    // sequential recurrence (round-1-proven per-step kernel)
    for (int t = 0; t < NSTEP; t++)
        lstm_step<<<128, 256, LSTM_SMEM>>>(W_hh, t);

    // output projection: [2016,512] @ [512,32000], scattered to out[b][t+1][:]
    gemm_tf32<1, VV><<<dim3(VV / 128, 16), 256>>>(fc_w, fc_b, nullptr, out);
}

// round 13
// speedup vs baseline: 1.1799x; 1.1210x over previous
#include <cuda_runtime.h>
#include <cuda_fp16.h>
#include <math.h>
#include <stdint.h>

// Problem constants
#define BB 32
#define TT 64
#define EE 512
#define HH 512
#define VV 32000
#define NSTEP 63              // T-1 timesteps
#define MM (NSTEP * BB)       // 2016 rows
#define G4 (4 * HH)           // 2048 gate columns
#define KK 512

// -------------------- device scratch (no allocs allowed) --------------------
__device__ float g_xseq[MM * EE];          // [63*32][512]  LSTM inputs
__device__ float g_pre[(size_t)MM * G4];   // [2016][2048]  pre-gates (x@W_ih^T + biases)
__device__ float g_hs[MM * HH];            // [2016][512]   hidden states per step
__device__ float g_h[2][BB * HH];          // double-buffered h (cross-CTA race safety)
__device__ float g_c[BB * HH];             // cell state (CTA-private columns)
__device__ int   g_cap64;                  // 1 if captions buffer is int64

// -------------------- dtype detect for captions --------------------
__global__ void detect_cap64(const int* cap) {
    if (threadIdx.x == 0) {
        int f = 1;
        for (int i = 0; i < 32; i++)
            if (cap[2 * i + 1] != 0) { f = 0; break; }
        g_cap64 = f;
    }
}

// -------------------- init h/c to zero (every launch: graph-replay determinism) ----
__global__ void init_state() {
    int i = blockIdx.x * blockDim.x + threadIdx.x;
    if (i < BB * HH) { g_h[0][i] = 0.f; g_c[i] = 0.f; }
}

// -------------------- zero out[:, 0, :] --------------------
__global__ void zero_out0(float* out) {
    int b  = blockIdx.y;
    int vv = blockIdx.x * 256 + threadIdx.x;
    if (vv < VV) out[(size_t)b * TT * VV + vv] = 0.f;
}

// -------------------- build x_seq: [t=0]=features, [t>=1]=embed(captions[:,t+1]) ----
__global__ void build_xseq(const float* __restrict__ features,
                           const void*  __restrict__ cap,
                           const float* __restrict__ embed) {
    int i = blockIdx.x;   // 0..62
    int b = blockIdx.y;   // 0..31
    int col = threadIdx.x * 4;
    const float* src;
    if (i == 0) {
        src = features + (size_t)b * EE;
    } else {
        long long idx;
        if (g_cap64) idx = ((const long long*)cap)[b * TT + i + 1];
        else         idx = ((const int*)cap)[b * TT + i + 1];
        src = embed + (size_t)idx * EE;
    }
    *(float4*)&g_xseq[((size_t)i * BB + b) * EE + col] = *(const float4*)&src[col];
}

// -------------------- fp16 pack helper --------------------
// u32 = fp16x2{low = e0, high = e1}; element 2j goes in the LOW half,
// matching the m16n8k16 fragment convention (first element = low 16 bits).
__device__ __forceinline__ uint32_t f2h2(float e0, float e1) {
    union { __half2 h; uint32_t u; } x;
    x.h = __floats2half2_rn(e0, e1);
    return x.u;
}

// -------------------- fp16 GEMM: out = A @ B^T + bias --------------------
// R11-PROVEN structure with the MMA shape widened m16n8k8.tf32 -> m16n8k16.f16.
// fp16 has the same 10-bit explicit mantissa as tf32 and products accumulate
// in fp32, so accuracy matches the proven tf32 path while instruction count
// halves. Fragment smem indexing is structurally identical (u32 = fp16x2 pair).
// A row-major [M, 512] (device global picked by MODE), B row-major [N, 512].
// MODE 0: A=g_xseq, out=g_pre[m][n],              bias = bias1[n]+bias2[n]
// MODE 1: A=g_hs,   out=d_out[(b*64 + t+1)][n],   bias = bias1[n]   (m = t*32+b)
template <int MODE, int N>
__global__ void __launch_bounds__(256)
gemm_f16(const float* __restrict__ Bmat,
         const float* __restrict__ bias1,
         const float* __restrict__ bias2,
         float* __restrict__ outc) {
    constexpr int BM = 128, BN = 128, BK = 32;      // BK in fp16 elements = 16 u32
    __shared__ uint32_t sA[BM][16 + 4];
    __shared__ uint32_t sB[BN][16 + 4];

    const float* Amat = (MODE == 0) ? g_xseq : g_hs;
    float*       Out  = (MODE == 0) ? g_pre  : outc;

    int tid  = threadIdx.x;
    int wid  = tid >> 5, lane = tid & 31;
    int wm   = wid & 3,  wn   = wid >> 2;      // 4x2 warp grid, warp tile 32x64
    int grp  = lane >> 2, tig = lane & 3;
    int m0   = blockIdx.y * BM, n0 = blockIdx.x * BN;

    float c[2][8][4];
#pragma unroll
    for (int mi = 0; mi < 2; mi++)
#pragma unroll
        for (int ni = 0; ni < 8; ni++)
#pragma unroll
            for (int r = 0; r < 4; r++) c[mi][ni][r] = 0.f;

    for (int kt = 0; kt < KK / BK; kt++) {          // 16 tiles
        int k0 = kt * BK;
        // global fp32 -> fp16x2 regs (A and B use the same proven slot map:
        // slot s: row = s>>2, qc = s&3 -> u32 cols [qc*4, qc*4+4) = elements
        // [qc*8, qc*8+8) of this k-tile)
        uint4 apack[2], bpack[2]; int lrow[2], lqc[2];
#pragma unroll
        for (int l = 0; l < 2; l++) {
            int s = tid + l * 256;            // 0..511
            int r = s >> 2, qc = s & 3;
            lrow[l] = r; lqc[l] = qc;
            int gm = m0 + r;
            float4 a0, a1;
            if (gm < MM) {
                const float* ap = &Amat[(size_t)gm * KK + k0 + qc * 8];
                a0 = *(const float4*)ap;
                a1 = *(const float4*)(ap + 4);
            } else {
                a0 = make_float4(0.f, 0.f, 0.f, 0.f);
                a1 = a0;
            }
            apack[l].x = f2h2(a0.x, a0.y); apack[l].y = f2h2(a0.z, a0.w);
            apack[l].z = f2h2(a1.x, a1.y); apack[l].w = f2h2(a1.z, a1.w);
            const float* bp = &Bmat[(size_t)(n0 + r) * KK + k0 + qc * 8];
            float4 b0 = *(const float4*)bp;
            float4 b1 = *(const float4*)(bp + 4);
            bpack[l].x = f2h2(b0.x, b0.y); bpack[l].y = f2h2(b0.z, b0.w);
            bpack[l].z = f2h2(b1.x, b1.y); bpack[l].w = f2h2(b1.z, b1.w);
        }

        __syncthreads();   // previous iter's compute done before overwrite
#pragma unroll
        for (int l = 0; l < 2; l++) {
            *(uint4*)&sA[lrow[l]][lqc[l] * 4] = apack[l];
            *(uint4*)&sB[lrow[l]][lqc[l] * 4] = bpack[l];
        }
        __syncthreads();

#pragma unroll
        for (int ks = 0; ks < 2; ks++) {      // two k16 halves of the 32-tile
            int kk = ks * 8;                  // u32 column offset
            uint32_t a[2][4], bf[8][2];
#pragma unroll
            for (int mi = 0; mi < 2; mi++) {
                int mr = wm * 32 + mi * 16;
                // {row grp, k-lo}, {row grp+8, k-lo}, {row grp, k-hi}, {row grp+8, k-hi}
                a[mi][0] = sA[mr + grp][kk + tig];
                a[mi][1] = sA[mr + grp + 8][kk + tig];
                a[mi][2] = sA[mr + grp][kk + tig + 4];
                a[mi][3] = sA[mr + grp + 8][kk + tig + 4];
            }
#pragma unroll
            for (int ni = 0; ni < 8; ni++) {
                int nr = wn * 64 + ni * 8;
                bf[ni][0] = sB[nr + grp][kk + tig];
                bf[ni][1] = sB[nr + grp][kk + tig + 4];
            }
#pragma unroll
            for (int mi = 0; mi < 2; mi++)
#pragma unroll
                for (int ni = 0; ni < 8; ni++) {
                    asm volatile(
                        "mma.sync.aligned.m16n8k16.row.col.f32.f16.f16.f32 "
                        "{%0,%1,%2,%3}, {%4,%5,%6,%7}, {%8,%9}, {%0,%1,%2,%3};"
                        : "+f"(c[mi][ni][0]), "+f"(c[mi][ni][1]),
                          "+f"(c[mi][ni][2]), "+f"(c[mi][ni][3])
                        : "r"(a[mi][0]), "r"(a[mi][1]), "r"(a[mi][2]), "r"(a[mi][3]),
                          "r"(bf[ni][0]), "r"(bf[ni][1]));
                }
        }
    }

    // epilogue (R11-proven; C fragment layout identical across mma shapes)
#pragma unroll
    for (int mi = 0; mi < 2; mi++) {
#pragma unroll
        for (int ni = 0; ni < 8; ni++) {
            int col = n0 + wn * 64 + ni * 8 + tig * 2;
            float bs0 = bias1[col]     + (MODE == 0 ? bias2[col]     : 0.f);
            float bs1 = bias1[col + 1] + (MODE == 0 ? bias2[col + 1] : 0.f);
#pragma unroll
            for (int half = 0; half < 2; half++) {
                int mrow = m0 + wm * 32 + mi * 16 + grp + half * 8;
                if (mrow < MM) {
                    size_t off;
                    if (MODE == 0) {
                        off = (size_t)mrow * N;
                    } else {
                        int t = mrow >> 5, b = mrow & 31;
                        off = ((size_t)(b * TT + t + 1)) * N;
                    }
                    Out[off + col]     = c[mi][ni][half * 2 + 0] + bs0;
                    Out[off + col + 1] = c[mi][ni][half * 2 + 1] + bs1;
                }
            }
        }
    }
}

// -------------------- LSTM step (ROUND-1 PROVEN, fp32, per-step launch) ----------
// grid 128 CTAs (4 hidden units each), 256 threads (8 warps).
// Warp w computes gate rows r = 2w, 2w+1 of this CTA's 16 gate rows,
// for all 32 batches (lane = batch). r = g*4 + du, j = g*512 + (cta*4+du).
#define LSTM_SMEM ((32 * 516 + 16 * 32) * 4)

__global__ void lstm_step(const float* __restrict__ Whh, int t) {
    extern __shared__ float sm[];
    float* shh = sm;             // [32][516] padded h (prev step)
    float* sg  = sm + 32 * 516;  // [16][32] gate values

    int tid = threadIdx.x;
    const float* hin = g_h[t & 1];
#pragma unroll
    for (int i = 0; i < 16; i++) {
        int s = tid + i * 256;           // 4096 float4 slots
        int row = s >> 7, c4 = s & 127;
        float4 v = *(const float4*)&hin[row * 512 + c4 * 4];
        *(float4*)&shh[row * 516 + c4 * 4] = v;
    }
    __syncthreads();

    int wid = tid >> 5, lane = tid & 31;
#pragma unroll
    for (int rr = 0; rr < 2; rr++) {
        int r = wid * 2 + rr;
        int gidx = r >> 2, du = r & 3;
        int u = blockIdx.x * 4 + du;
        int j = gidx * 512 + u;
        const float4* wp = (const float4*)(Whh + (size_t)j * 512);
        const float4* hp = (const float4*)&shh[lane * 516];
        float acc = 0.f;
#pragma unroll 4
        for (int kkk = 0; kkk < 128; kkk++) {
            float4 w4 = __ldg(&wp[kkk]);    // uniform across warp (broadcast)
            float4 h4 = hp[kkk];
            acc += w4.x * h4.x + w4.y * h4.y + w4.z * h4.z + w4.w * h4.w;
        }
        acc += g_pre[((size_t)t * 32 + lane) * (size_t)G4 + j];
        sg[r * 32 + lane] = acc;
    }
    __syncthreads();

    if (tid < 128) {
        int du = tid >> 5, b = tid & 31;
        int u  = blockIdx.x * 4 + du;
        float gi = sg[(0 + du) * 32 + b];
        float gf = sg[(4 + du) * 32 + b];
        float gg = sg[(8 + du) * 32 + b];
        float go = sg[(12 + du) * 32 + b];
        float si = 1.f / (1.f + __expf(-gi));
        float sf = 1.f / (1.f + __expf(-gf));
        float so = 1.f / (1.f + __expf(-go));
        float tg = tanhf(gg);
        float cn = sf * g_c[b * 512 + u] + si * tg;
        float hn = so * tanhf(cn);
        g_c[b * 512 + u] = cn;
        g_h[(t + 1) & 1][b * 512 + u] = hn;
        g_hs[((size_t)t * 32 + b) * 512 + u] = hn;
    }
}

// -------------------- launch --------------------
extern "C" void kernel_launch(void* const* d_in, const int* in_sizes, int n_in,
                              void* d_out, int out_size) {
    const float* features = (const float*)d_in[0];
    const void*  captions = d_in[1];
    const float* embed    = (const float*)d_in[2];
    const float* W_ih     = (const float*)d_in[3];
    const float* W_hh     = (const float*)d_in[4];
    const float* b_ih     = (const float*)d_in[5];
    const float* b_hh     = (const float*)d_in[6];
    const float* fc_w     = (const float*)d_in[7];
    const float* fc_b     = (const float*)d_in[8];
    float* out = (float*)d_out;

    cudaFuncSetAttribute(lstm_step, cudaFuncAttributeMaxDynamicSharedMemorySize,
                         LSTM_SMEM);

    // Order puts the pre-gate GEMM in the ncu-captured slot (my 4th launch).
    detect_cap64<<<1, 32>>>((const int*)captions);
    build_xseq<<<dim3(63, 32), 128>>>(features, captions, embed);
    init_state<<<64, 256>>>();

    // pre-gates for all timesteps: [2016,512] @ [512,2048] + b_ih + b_hh
    gemm_f16<0, G4><<<dim3(G4 / 128, 16), 256>>>(W_ih, b_ih, b_hh, nullptr);

    zero_out0<<<dim3(125, 32), 256>>>(out);

    // sequential recurrence (round-1-proven per-step kernel)
    for (int t = 0; t < NSTEP; t++)
        lstm_step<<<128, 256, LSTM_SMEM>>>(W_hh, t);

    // output projection: [2016,512] @ [512,32000], scattered to out[b][t+1][:]
    gemm_f16<1, VV><<<dim3(VV / 128, 16), 256>>>(fc_w, fc_b, nullptr, out);
}

// round 14
// speedup vs baseline: 1.2264x; 1.0394x over previous
#include <cuda_runtime.h>
#include <cuda_fp16.h>
#include <math.h>
#include <stdint.h>

// Problem constants
#define BB 32
#define TT 64
#define EE 512
#define HH 512
#define VV 32000
#define NSTEP 63              // T-1 timesteps
#define MM (NSTEP * BB)       // 2016 rows
#define G4 (4 * HH)           // 2048 gate columns
#define KK 512

// -------------------- device scratch (no allocs allowed) --------------------
__device__ float g_xseq[MM * EE];          // [63*32][512]  LSTM inputs
__device__ float g_pre[(size_t)MM * G4];   // [2016][2048]  pre-gates (x@W_ih^T + biases)
__device__ float g_hs[MM * HH];            // [2016][512]   hidden states per step
__device__ float g_h[2][BB * HH];          // double-buffered h (cross-CTA race safety)
__device__ float g_c[BB * HH];             // cell state (CTA-private columns)
__device__ int   g_cap64;                  // 1 if captions buffer is int64

// -------------------- dtype detect for captions --------------------
__global__ void detect_cap64(const int* cap) {
    if (threadIdx.x == 0) {
        int f = 1;
        for (int i = 0; i < 32; i++)
            if (cap[2 * i + 1] != 0) { f = 0; break; }
        g_cap64 = f;
    }
}

// -------------------- init h/c to zero (every launch: graph-replay determinism) ----
__global__ void init_state() {
    int i = blockIdx.x * blockDim.x + threadIdx.x;
    if (i < BB * HH) { g_h[0][i] = 0.f; g_c[i] = 0.f; }
}

// -------------------- zero out[:, 0, :] --------------------
__global__ void zero_out0(float* out) {
    int b  = blockIdx.y;
    int vv = blockIdx.x * 256 + threadIdx.x;
    if (vv < VV) out[(size_t)b * TT * VV + vv] = 0.f;
}

// -------------------- build x_seq: [t=0]=features, [t>=1]=embed(captions[:,t+1]) ----
__global__ void build_xseq(const float* __restrict__ features,
                           const void*  __restrict__ cap,
                           const float* __restrict__ embed) {
    int i = blockIdx.x;   // 0..62
    int b = blockIdx.y;   // 0..31
    int col = threadIdx.x * 4;
    const float* src;
    if (i == 0) {
        src = features + (size_t)b * EE;
    } else {
        long long idx;
        if (g_cap64) idx = ((const long long*)cap)[b * TT + i + 1];
        else         idx = ((const int*)cap)[b * TT + i + 1];
        src = embed + (size_t)idx * EE;
    }
    *(float4*)&g_xseq[((size_t)i * BB + b) * EE + col] = *(const float4*)&src[col];
}

// -------------------- fp16 pack helper --------------------
__device__ __forceinline__ uint32_t f2h2(float e0, float e1) {
    union { __half2 h; uint32_t u; } x;
    x.h = __floats2half2_rn(e0, e1);
    return x.u;
}

// -------------------- fp16 GEMM: out = A @ B^T + bias --------------------
// R13-PROVEN math (fp16 m16n8k16, fp32 accum) with two scheduling-only changes:
//   (1) ldmatrix.x4 fragment loads (bit-identical values, 4x fewer smem instrs)
//   (2) double-buffered smem, ONE __syncthreads per k-tile, 2-deep LDG prefetch
// A row-major [M, 512] (device global picked by MODE), B row-major [N, 512].
// MODE 0: A=g_xseq, out=g_pre[m][n],              bias = bias1[n]+bias2[n]
// MODE 1: A=g_hs,   out=d_out[(b*64 + t+1)][n],   bias = bias1[n]   (m = t*32+b)
#define LDW 20        // u32 row stride in smem (16 + 4 pad)
template <int MODE, int N>
__global__ void __launch_bounds__(256)
gemm_f16(const float* __restrict__ Bmat,
         const float* __restrict__ bias1,
         const float* __restrict__ bias2,
         float* __restrict__ outc) {
    constexpr int BM = 128, BN = 128, BK = 32, NT = KK / BK;   // 16 tiles
    __shared__ uint32_t sA[2][BM][LDW];
    __shared__ uint32_t sB[2][BN][LDW];

    const float* Amat = (MODE == 0) ? g_xseq : g_hs;
    float*       Out  = (MODE == 0) ? g_pre  : outc;

    int tid  = threadIdx.x;
    int wid  = tid >> 5, lane = tid & 31;
    int wm   = wid & 3,  wn   = wid >> 2;      // 4x2 warp grid, warp tile 32x64
    int grp  = lane >> 2, tig = lane & 3;
    int m0   = blockIdx.y * BM, n0 = blockIdx.x * BN;

    // per-thread global load slots (2 per matrix): slot s -> row s>>2, qc s&3
    int lrow[2], lqc[2]; bool aval[2];
    const float *aptr[2], *bptr[2];
#pragma unroll
    for (int l = 0; l < 2; l++) {
        int s = tid + l * 256;
        lrow[l] = s >> 2; lqc[l] = s & 3;
        int gm = m0 + lrow[l];
        aval[l] = (gm < MM);
        aptr[l] = &Amat[(size_t)(aval[l] ? gm : 0) * KK + lqc[l] * 8];
        bptr[l] = &Bmat[(size_t)(n0 + lrow[l]) * KK + lqc[l] * 8];
    }

    // ldmatrix per-thread source offsets (u32 units within a buffer)
    //   A tile (mi,ks): row = wm*32 + mi*16 + (lane&15), col = ks*8 + (lane>>4)*4
    //   B tile (nj,ks): row = wn*64 + nj*16 + (lane>>4)*8 + (lane&7),
    //                   col = ks*8 + ((lane>>3)&1)*4
    uint32_t sA0 = (uint32_t)__cvta_generic_to_shared(&sA[0][0][0]);
    uint32_t sB0 = (uint32_t)__cvta_generic_to_shared(&sB[0][0][0]);
    uint32_t aoff = (uint32_t)((wm * 32 + (lane & 15)) * LDW + (lane >> 4) * 4);
    uint32_t boff = (uint32_t)((wn * 64 + (lane >> 4) * 8 + (lane & 7)) * LDW
                               + ((lane >> 3) & 1) * 4);

    float c[2][8][4];
#pragma unroll
    for (int mi = 0; mi < 2; mi++)
#pragma unroll
        for (int ni = 0; ni < 8; ni++)
#pragma unroll
            for (int r = 0; r < 4; r++) c[mi][ni][r] = 0.f;

    uint4 apack[2], bpack[2];

    // ---- pipeline helpers (macros keep regs tight) ----
#define LOADREGS(KT) do {                                                     \
        int k0 = (KT) * BK;                                                   \
        _Pragma("unroll")                                                     \
        for (int l = 0; l < 2; l++) {                                         \
            float4 a0, a1;                                                    \
            if (aval[l]) {                                                    \
                a0 = *(const float4*)(aptr[l] + k0);                          \
                a1 = *(const float4*)(aptr[l] + k0 + 4);                      \
            } else { a0 = make_float4(0.f,0.f,0.f,0.f); a1 = a0; }            \
            apack[l].x = f2h2(a0.x, a0.y); apack[l].y = f2h2(a0.z, a0.w);     \
            apack[l].z = f2h2(a1.x, a1.y); apack[l].w = f2h2(a1.z, a1.w);     \
            float4 b0 = *(const float4*)(bptr[l] + k0);                       \
            float4 b1 = *(const float4*)(bptr[l] + k0 + 4);                   \
            bpack[l].x = f2h2(b0.x, b0.y); bpack[l].y = f2h2(b0.z, b0.w);     \
            bpack[l].z = f2h2(b1.x, b1.y); bpack[l].w = f2h2(b1.z, b1.w);     \
        }                                                                     \
    } while (0)
#define STOREST(BUF) do {                                                     \
        _Pragma("unroll")                                                     \
        for (int l = 0; l < 2; l++) {                                         \
            *(uint4*)&sA[BUF][lrow[l]][lqc[l] * 4] = apack[l];                \
            *(uint4*)&sB[BUF][lrow[l]][lqc[l] * 4] = bpack[l];                \
        }                                                                     \
    } while (0)

    // prologue: tile0 -> buf0; tile1 -> regs
    LOADREGS(0);
    STOREST(0);
    LOADREGS(1);
    __syncthreads();

#pragma unroll 1
    for (int kt = 0; kt < NT; kt++) {
        int cb = kt & 1;
        if (kt + 1 < NT) STOREST((kt + 1) & 1);   // other buffer: safe post-sync
        if (kt + 2 < NT) LOADREGS(kt + 2);        // 2-deep global prefetch

        uint32_t sAb = sA0 + (uint32_t)(cb * BM * LDW * 4);
        uint32_t sBb = sB0 + (uint32_t)(cb * BN * LDW * 4);
#pragma unroll
        for (int ks = 0; ks < 2; ks++) {
            uint32_t kadd = (uint32_t)(ks * 8 * 4);
            uint32_t a[2][4], bf[8][2];
#pragma unroll
            for (int mi = 0; mi < 2; mi++) {
                uint32_t addr = sAb + (aoff + (uint32_t)(mi * 16 * LDW)) * 4 + kadd;
                asm volatile(
                    "ldmatrix.sync.aligned.m8n8.x4.shared.b16 {%0,%1,%2,%3}, [%4];"
                    : "=r"(a[mi][0]), "=r"(a[mi][1]), "=r"(a[mi][2]), "=r"(a[mi][3])
                    : "r"(addr));
            }
#pragma unroll
            for (int nj = 0; nj < 4; nj++) {
                uint32_t addr = sBb + (boff + (uint32_t)(nj * 16 * LDW)) * 4 + kadd;
                asm volatile(
                    "ldmatrix.sync.aligned.m8n8.x4.shared.b16 {%0,%1,%2,%3}, [%4];"
                    : "=r"(bf[2 * nj][0]), "=r"(bf[2 * nj][1]),
                      "=r"(bf[2 * nj + 1][0]), "=r"(bf[2 * nj + 1][1])
                    : "r"(addr));
            }
#pragma unroll
            for (int mi = 0; mi < 2; mi++)
#pragma unroll
                for (int ni = 0; ni < 8; ni++) {
                    asm volatile(
                        "mma.sync.aligned.m16n8k16.row.col.f32.f16.f16.f32 "
                        "{%0,%1,%2,%3}, {%4,%5,%6,%7}, {%8,%9}, {%0,%1,%2,%3};"
                        : "+f"(c[mi][ni][0]), "+f"(c[mi][ni][1]),
                          "+f"(c[mi][ni][2]), "+f"(c[mi][ni][3])
                        : "r"(a[mi][0]), "r"(a[mi][1]), "r"(a[mi][2]), "r"(a[mi][3]),
                          "r"(bf[ni][0]), "r"(bf[ni][1]));
                }
        }
        __syncthreads();
    }
#undef LOADREGS
#undef STOREST

    // epilogue (R11/R13-proven; C fragment layout unchanged)
#pragma unroll
    for (int mi = 0; mi < 2; mi++) {
#pragma unroll
        for (int ni = 0; ni < 8; ni++) {
            int col = n0 + wn * 64 + ni * 8 + tig * 2;
            float bs0 = bias1[col]     + (MODE == 0 ? bias2[col]     : 0.f);
            float bs1 = bias1[col + 1] + (MODE == 0 ? bias2[col + 1] : 0.f);
#pragma unroll
            for (int half = 0; half < 2; half++) {
                int mrow = m0 + wm * 32 + mi * 16 + grp + half * 8;
                if (mrow < MM) {
                    size_t off;
                    if (MODE == 0) {
                        off = (size_t)mrow * N;
                    } else {
                        int t = mrow >> 5, b = mrow & 31;
                        off = ((size_t)(b * TT + t + 1)) * N;
                    }
                    Out[off + col]     = c[mi][ni][half * 2 + 0] + bs0;
                    Out[off + col + 1] = c[mi][ni][half * 2 + 1] + bs1;
                }
            }
        }
    }
}

// -------------------- LSTM step (ROUND-1 PROVEN, fp32, per-step launch) ----------
#define LSTM_SMEM ((32 * 516 + 16 * 32) * 4)

__global__ void lstm_step(const float* __restrict__ Whh, int t) {
    extern __shared__ float sm[];
    float* shh = sm;             // [32][516] padded h (prev step)
    float* sg  = sm + 32 * 516;  // [16][32] gate values

    int tid = threadIdx.x;
    const float* hin = g_h[t & 1];
#pragma unroll
    for (int i = 0; i < 16; i++) {
        int s = tid + i * 256;           // 4096 float4 slots
        int row = s >> 7, c4 = s & 127;
        float4 v = *(const float4*)&hin[row * 512 + c4 * 4];
        *(float4*)&shh[row * 516 + c4 * 4] = v;
    }
    __syncthreads();

    int wid = tid >> 5, lane = tid & 31;
#pragma unroll
    for (int rr = 0; rr < 2; rr++) {
        int r = wid * 2 + rr;
        int gidx = r >> 2, du = r & 3;
        int u = blockIdx.x * 4 + du;
        int j = gidx * 512 + u;
        const float4* wp = (const float4*)(Whh + (size_t)j * 512);
        const float4* hp = (const float4*)&shh[lane * 516];
        float acc = 0.f;
#pragma unroll 4
        for (int kkk = 0; kkk < 128; kkk++) {
            float4 w4 = __ldg(&wp[kkk]);    // uniform across warp (broadcast)
            float4 h4 = hp[kkk];
            acc += w4.x * h4.x + w4.y * h4.y + w4.z * h4.z + w4.w * h4.w;
        }
        acc += g_pre[((size_t)t * 32 + lane) * (size_t)G4 + j];
        sg[r * 32 + lane] = acc;
    }
    __syncthreads();

    if (tid < 128) {
        int du = tid >> 5, b = tid & 31;
        int u  = blockIdx.x * 4 + du;
        float gi = sg[(0 + du) * 32 + b];
        float gf = sg[(4 + du) * 32 + b];
        float gg = sg[(8 + du) * 32 + b];
        float go = sg[(12 + du) * 32 + b];
        float si = 1.f / (1.f + __expf(-gi));
        float sf = 1.f / (1.f + __expf(-gf));
        float so = 1.f / (1.f + __expf(-go));
        float tg = tanhf(gg);
        float cn = sf * g_c[b * 512 + u] + si * tg;
        float hn = so * tanhf(cn);
        g_c[b * 512 + u] = cn;
        g_h[(t + 1) & 1][b * 512 + u] = hn;
        g_hs[((size_t)t * 32 + b) * 512 + u] = hn;
    }
}

// -------------------- launch --------------------
extern "C" void kernel_launch(void* const* d_in, const int* in_sizes, int n_in,
                              void* d_out, int out_size) {
    const float* features = (const float*)d_in[0];
    const void*  captions = d_in[1];
    const float* embed    = (const float*)d_in[2];
    const float* W_ih     = (const float*)d_in[3];
    const float* W_hh     = (const float*)d_in[4];
    const float* b_ih     = (const float*)d_in[5];
    const float* b_hh     = (const float*)d_in[6];
    const float* fc_w     = (const float*)d_in[7];
    const float* fc_b     = (const float*)d_in[8];
    float* out = (float*)d_out;

    cudaFuncSetAttribute(lstm_step, cudaFuncAttributeMaxDynamicSharedMemorySize,
                         LSTM_SMEM);

    // Same order as R13 (gemm<0> sat in the profiled slot there).
    detect_cap64<<<1, 32>>>((const int*)captions);
    build_xseq<<<dim3(63, 32), 128>>>(features, captions, embed);
    init_state<<<64, 256>>>();

    // pre-gates for all timesteps: [2016,512] @ [512,2048] + b_ih + b_hh
    gemm_f16<0, G4><<<dim3(G4 / 128, 16), 256>>>(W_ih, b_ih, b_hh, nullptr);

    zero_out0<<<dim3(125, 32), 256>>>(out);

    // sequential recurrence (round-1-proven per-step kernel)
    for (int t = 0; t < NSTEP; t++)
        lstm_step<<<128, 256, LSTM_SMEM>>>(W_hh, t);

    // output projection: [2016,512] @ [512,32000], scattered to out[b][t+1][:]
    gemm_f16<1, VV><<<dim3(VV / 128, 16), 256>>>(fc_w, fc_b, nullptr, out);
}